// round 12
// baseline (speedup 1.0000x reference)
#include <cuda_runtime.h>
#include <cuda_fp16.h>
#include <math.h>
#include <stdint.h>

// ---------------------------------------------------------------------------
// AIO_DownsampleCouplingBlock — Round 12: 128-thread CTAs, 4 CTAs/SM.
// BM=128, BN=64 (32 lo + 32 paired hi), warp grid 2x2, fused affine epilogue.
// ---------------------------------------------------------------------------

__device__ __align__(16) __half g_xh[32 * 64 * 64 * 48];    // x1 NHWC half
__device__ __align__(16) __half g_y2h[32 * 32 * 32 * 192];  // y2 NHWC half
__device__ __align__(16) __half g_wp1[9 * 384 * 48];        // conv1 w [st][nn][48]
__device__ __align__(16) __half g_wp2[54 * 384 * 32];       // conv2 w [st][nn][32]
__device__ int   g_invperm[384];
__device__ float g_scale[384];

__device__ __forceinline__ void cp_async16(unsigned dst, const void* src) {
    asm volatile("cp.async.cg.shared.global [%0], [%1], 16;\n"
                 :: "r"(dst), "l"(src));
}
__device__ __forceinline__ void cp_async16z(unsigned dst, const void* src, int sz) {
    asm volatile("cp.async.cg.shared.global [%0], [%1], 16, %2;\n"
                 :: "r"(dst), "l"(src), "r"(sz));
}
__device__ __forceinline__ void ldsm4(uint32_t& r0, uint32_t& r1,
                                      uint32_t& r2, uint32_t& r3, unsigned addr) {
    asm volatile("ldmatrix.sync.aligned.m8n8.x4.shared.b16 {%0,%1,%2,%3}, [%4];"
                 : "=r"(r0), "=r"(r1), "=r"(r2), "=r"(r3) : "r"(addr));
}

// ---------------------------------------------------------------------------
__global__ void prep_kernel(const float* __restrict__ perm_w,
                            const float* __restrict__ act_norm) {
    int p = threadIdx.x;
    if (p < 384) {
        int o_found = 0;
        for (int o = 0; o < 384; ++o)
            if (perm_w[o * 384 + p] > 0.5f) o_found = o;
        g_invperm[p] = o_found;
        g_scale[p] = 0.2f * log1pf(expf(0.5f * act_norm[p]));
    }
}

// nn remap for BN=64 blocks: block y = nn/64, r = nn%64:
//   r < 32 : n = y*32 + r ; r >= 32 : n = 192 + y*32 + (r-32)
__device__ __forceinline__ int nn_to_n(int nn) {
    int y = nn >> 6, r = nn & 63;
    return (r < 32) ? (y * 32 + r) : (192 + y * 32 + (r - 32));
}

// both weight packs: dst[st][nn(384)][k(KB)], exact K (no pad)
__global__ void pack_all_kernel(const float* __restrict__ w_hi,
                                const float* __restrict__ w_lo) {
    const int T1 = 9 * 384 * 48;
    const int T2 = 54 * 384 * 32;
    int idx = blockIdx.x * 256 + threadIdx.x;
    if (idx < T1) {
        int k = idx % 48;
        int nn = (idx / 48) % 384;
        int tap = idx / (48 * 384);
        int n = nn_to_n(nn);
        g_wp1[idx] = __float2half(w_hi[(n * 48 + k) * 9 + tap]);
    } else if (idx < T1 + T2) {
        int j = idx - T1;
        int k = j % 32;
        int nn = (j / 32) % 384;
        int st = j / (32 * 384);          // tap = st/6, cblk = st%6
        int n = nn_to_n(nn);
        int tap = st / 6;
        int c = (st % 6) * 32 + k;
        g_wp2[j] = __float2half(w_lo[(n * 192 + c) * 9 + tap]);
    }
}

// x (NCHW f32, first 48 channels) -> g_xh (NHWC half), half2 stores
__global__ __launch_bounds__(256) void x2h_kernel(const float* __restrict__ x) {
    __shared__ float tile[48][65];
    const int b = blockIdx.x >> 6, h = blockIdx.x & 63;
    for (int idx = threadIdx.x; idx < 48 * 64; idx += 256) {
        const int c = idx >> 6, w = idx & 63;
        tile[c][w] = x[(((size_t)b * 96 + c) * 64 + h) * 64 + w];
    }
    __syncthreads();
    for (int idx = threadIdx.x; idx < 64 * 24; idx += 256) {
        const int w = idx / 24, cp = idx % 24;
        __half2 v = __floats2half2_rn(tile[2 * cp][w], tile[2 * cp + 1][w]);
        *(__half2*)&g_xh[(((size_t)b * 64 + h) * 64 + w) * 48 + 2 * cp] = v;
    }
}

// ---------------------------------------------------------------------------
// fused implicit-GEMM conv + affine epilogue.
// 128 threads / 4 warps, 4 CTAs/SM. Warp grid 2(M) x 2(N), warp tile 64x32.
// A smem [m(128)][KB halves], B smem [nn(64)][KB], rows padded +16B.
// N-block yb (0..5): 32 lo + 32 paired hi channels.
// ---------------------------------------------------------------------------
template <int KB, int NST, int CH, int STRIDE, int HIN, int CTOT, int WHICH>
__global__ __launch_bounds__(128, 4) void conv_fused(
    const float* __restrict__ x,
    const float* __restrict__ bias,
    const float* __restrict__ act_offset,
    float* __restrict__ outp) {
    extern __shared__ __align__(16) char smem[];

    constexpr int ROWB   = KB * 2 + 16;      // bytes per smem row
    constexpr int ASTG   = 128 * ROWB;
    constexpr int BSTG   = 64 * ROWB;
    constexpr int STGB   = ASTG + BSTG;
    constexpr int KSTEPS = KB / 16;
    constexpr int CHK    = KB / 8;           // 16B chunks per row
    constexpr int NIT    = 9 * CH;

    const __half* inp = (WHICH == 1) ? (const __half*)g_xh : (const __half*)g_y2h;
    const __half* wp  = (WHICH == 1) ? (const __half*)g_wp1 : (const __half*)g_wp2;
    constexpr int XOFF  = (WHICH == 1) ? 48 : 0;
    constexpr int PBASE = (WHICH == 1) ? 192 : 0;

    const int tid  = threadIdx.x;
    const int lane = tid & 31;
    const int warp = tid >> 5;
    const int wm = warp >> 1;                // 0..1
    const int wn = warp & 1;                 // 0..1
    const int g4 = lane >> 2;
    const int t4 = lane & 3;

    const int bm   = blockIdx.x;
    const int bimg = bm >> 3;
    const int h0   = (bm & 7) * 4;
    const int yb   = blockIdx.y;             // 0..5
    const int n0   = yb * 64;

    const unsigned smemBase = (unsigned)__cvta_generic_to_shared(smem);
    const int aRowL = wm * 64 + (lane & 15);
    const int aKoffL = (lane >> 4) << 4;
    const int bRow0 = wn * 16 + ((lane >> 4) << 3) + (lane & 7);
    const int bKoffL = ((lane >> 3) & 1) << 4;

    float acc[4][4][4];
#pragma unroll
    for (int i = 0; i < 4; i++)
#pragma unroll
        for (int j = 0; j < 4; j++)
#pragma unroll
            for (int k = 0; k < 4; k++) acc[i][j][k] = 0.f;

    auto load_stage = [&](int it, int s) {
        const int tap = it / CH;
        const int c0  = (it - tap * CH) * KB;
        const int dh = tap / 3 - 1;
        const int dw = tap % 3 - 1;
        const unsigned aB = smemBase + s * STGB;
        const unsigned bB = aB + ASTG;
        // A: 128 rows x CHK chunks, 128 threads -> CHK tasks/thread
#pragma unroll
        for (int p = 0; p < CHK; ++p) {
            const int task = tid + 128 * p;
            const int row = task / CHK;
            const int ch  = task - row * CHK;
            const int h = h0 + (row >> 5);
            const int w = row & 31;
            const int ih = h * STRIDE + dh;
            const int iw = w * STRIDE + dw;
            const bool ok = (ih >= 0) && (ih < HIN) && (iw >= 0) && (iw < HIN);
            const __half* src = ok
                ? inp + ((size_t)(bimg * HIN + ih) * HIN + iw) * CTOT + c0 + ch * 8
                : inp;
            cp_async16z(aB + (unsigned)(row * ROWB + ch * 16), src, ok ? 16 : 0);
        }
        // B: 64 rows x CHK chunks -> CHK/2 tasks/thread
        const __half* wsrc = wp + (size_t)it * (384 * KB) + (size_t)n0 * KB;
#pragma unroll
        for (int p = 0; p < CHK / 2; ++p) {
            const int task = tid + 128 * p;
            const int row = task / CHK;
            const int ch  = task - row * CHK;
            cp_async16(bB + (unsigned)(row * ROWB + ch * 16), wsrc + row * KB + ch * 8);
        }
    };

    // prologue: NST-1 stages in flight
#pragma unroll
    for (int ps = 0; ps < NST - 1; ++ps) {
        load_stage(ps, ps);
        asm volatile("cp.async.commit_group;\n" ::: "memory");
    }

    int s = 0;
#pragma unroll 1
    for (int it = 0; it < NIT; ++it) {
        int wgn = NIT - 1 - it;
        if (wgn > NST - 2) wgn = NST - 2;
        if (wgn <= 0)
            asm volatile("cp.async.wait_group 0;\n" ::: "memory");
        else if (wgn == 1)
            asm volatile("cp.async.wait_group 1;\n" ::: "memory");
        else if (wgn == 2)
            asm volatile("cp.async.wait_group 2;\n" ::: "memory");
        else
            asm volatile("cp.async.wait_group 3;\n" ::: "memory");
        __syncthreads();

        if (it + NST - 1 < NIT) {
            int sw = s - 1; if (sw < 0) sw += NST;   // == (it+NST-1) % NST
            load_stage(it + NST - 1, sw);
            asm volatile("cp.async.commit_group;\n" ::: "memory");
        }

        const unsigned aB = smemBase + s * STGB;
        const unsigned bB = aB + ASTG;
#pragma unroll
        for (int step = 0; step < KSTEPS; ++step) {
            const int kb = step * 32;
            uint32_t af[4][4];
#pragma unroll
            for (int mi = 0; mi < 4; ++mi)
                ldsm4(af[mi][0], af[mi][1], af[mi][2], af[mi][3],
                      aB + (unsigned)((aRowL + mi * 16) * ROWB + kb + aKoffL));
            uint32_t bf[4][2];
            ldsm4(bf[0][0], bf[0][1], bf[1][0], bf[1][1],
                  bB + (unsigned)(bRow0 * ROWB + kb + bKoffL));
            ldsm4(bf[2][0], bf[2][1], bf[3][0], bf[3][1],
                  bB + (unsigned)((bRow0 + 32) * ROWB + kb + bKoffL));
#pragma unroll
            for (int mi = 0; mi < 4; ++mi)
#pragma unroll
                for (int ni = 0; ni < 4; ++ni) {
                    asm volatile(
                        "mma.sync.aligned.m16n8k16.row.col.f32.f16.f16.f32 "
                        "{%0,%1,%2,%3}, {%4,%5,%6,%7}, {%8,%9}, {%0,%1,%2,%3};"
                        : "+f"(acc[mi][ni][0]), "+f"(acc[mi][ni][1]),
                          "+f"(acc[mi][ni][2]), "+f"(acc[mi][ni][3])
                        : "r"(af[mi][0]), "r"(af[mi][1]),
                          "r"(af[mi][2]), "r"(af[mi][3]),
                          "r"(bf[ni][0]), "r"(bf[ni][1]));
                }
        }
        if (++s == NST) s = 0;
    }

    // ---- fused affine epilogue -------------------------------------------
    // ni in {0,1}: lo channel c = yb*32 + wn*16 + ni*8 + 2*t4 (+0/1)
    // paired hi accumulator at ni+2 (channel c+192)
#pragma unroll
    for (int ni = 0; ni < 2; ++ni) {
        const int c = yb * 32 + wn * 16 + ni * 8 + 2 * t4;   // even
        const float bl0 = bias[c],        bl1 = bias[c + 1];
        const float bh0 = bias[c + 192],  bh1 = bias[c + 193];
        const int p0 = PBASE + c, p1 = PBASE + c + 1;
        const float sc0 = g_scale[p0], sc1 = g_scale[p1];
        const float ao0 = act_offset[p0], ao1 = act_offset[p1];
        const int o0 = g_invperm[p0], o1 = g_invperm[p1];
        const int cc = c >> 2, ii = (c >> 1) & 1;
        const float* xrowb = x + (((size_t)bimg * 96 + XOFF + cc) * 64 + ii) * 64;
#pragma unroll
        for (int mi = 0; mi < 4; ++mi) {
#pragma unroll
            for (int rr = 0; rr < 2; ++rr) {
                const int m = wm * 64 + mi * 16 + g4 + rr * 8;
                const int h = h0 + (m >> 5);
                const int w = m & 31;
                const float lo0 = acc[mi][ni][rr * 2 + 0] + bl0;
                const float lo1 = acc[mi][ni][rr * 2 + 1] + bl1;
                const float hi0 = acc[mi][ni + 2][rr * 2 + 0] + bh0;
                const float hi1 = acc[mi][ni + 2][rr * 2 + 1] + bh1;
                const float2 xd = *(const float2*)&xrowb[(size_t)(2 * h) * 64 + 2 * w];
                const float y0 = xd.x * expf(2.0f * tanhf(0.2f * lo0)) + hi0;
                const float y1 = xd.y * expf(2.0f * tanhf(0.2f * lo1)) + hi1;
                const int hw = h * 32 + w;
                if (WHICH == 1) {
                    *(__half2*)&g_y2h[(((size_t)(bimg * 32 + h) * 32) + w) * 192 + c] =
                        __floats2half2_rn(y0, y1);
                }
                outp[(((size_t)(bimg * 384 + o0)) << 10) + hw] = y0 * sc0 + ao0;
                outp[(((size_t)(bimg * 384 + o1)) << 10) + hw] = y1 * sc1 + ao1;
            }
        }
    }
}

// ---------------------------------------------------------------------------
extern "C" void kernel_launch(void* const* d_in, const int* in_sizes, int n_in,
                              void* d_out, int out_size) {
    const float* x          = (const float*)d_in[0];
    const float* w_hi       = (const float*)d_in[1];
    const float* b_hi       = (const float*)d_in[2];
    const float* w_lo       = (const float*)d_in[3];
    const float* b_lo       = (const float*)d_in[4];
    const float* act_norm   = (const float*)d_in[5];
    const float* act_offset = (const float*)d_in[6];
    const float* perm_w     = (const float*)d_in[7];
    float* out = (float*)d_out;

    // conv1: KB=48, NST=2 -> stage 21,504 B, total 43,008 B  (4 CTAs/SM)
    // conv2: KB=32, NST=3 -> stage 15,360 B, total 46,080 B  (4 CTAs/SM)
    const int SMEM1 = 2 * 192 * (48 * 2 + 16);
    const int SMEM2 = 3 * 192 * (32 * 2 + 16);

    cudaFuncSetAttribute(conv_fused<48, 2, 1, 2, 64, 48, 1>,
                         cudaFuncAttributeMaxDynamicSharedMemorySize, SMEM1);
    cudaFuncSetAttribute(conv_fused<32, 3, 6, 1, 32, 192, 2>,
                         cudaFuncAttributeMaxDynamicSharedMemorySize, SMEM2);

    prep_kernel<<<1, 384>>>(perm_w, act_norm);
    {
        int total = 9 * 384 * 48 + 54 * 384 * 32;
        pack_all_kernel<<<(total + 255) / 256, 256>>>(w_hi, w_lo);
    }
    x2h_kernel<<<32 * 64, 256>>>(x);

    conv_fused<48, 2, 1, 2, 64, 48, 1><<<dim3(256, 6), 128, SMEM1>>>(
        x, b_hi, act_offset, out);

    conv_fused<32, 3, 6, 1, 32, 192, 2><<<dim3(256, 6), 128, SMEM2>>>(
        x, b_lo, act_offset, out);
}